// round 14
// baseline (speedup 1.0000x reference)
#include <cuda_runtime.h>
#include <cuda_bf16.h>
#include <math.h>

// Problem dims (fixed per reference)
#define ED   1024
#define GH   1024
#define NL   3
#define NH   8
#define HD   128
#define NN_  2048   // graph nodes
#define BB   1024   // batch

// ---------------- scratch (static device globals; no allocation) ----------------
__device__ float g_x [NN_*GH];
__device__ float g_Wh[NN_*GH];
__device__ float g_s1[NN_*NH];
__device__ float g_s2[NN_*NH];
__device__ float g_G [NN_*ED];
__device__ float g_Gr[NN_*ED];
__device__ float g_LG[NN_*ED];
__device__ float g_t1[BB*ED];
__device__ float g_t2[BB*ED];
__device__ float g_t3[BB*ED];
__device__ float g_t4[BB*ED];
__device__ float g_q [BB*ED];
__device__ float g_p [BB*ED];
__device__ float g_neg[BB*BB];
__device__ float g_infoRow[BB];
__device__ float g_lapRow[NN_];
__device__ float g_Wr[NL*ED*GH];      // rounded+reordered gatW (all layers)
__device__ float g_poWr[GH*ED];       // rounded poW
__device__ float g_laplr[NN_*NN_];    // rounded laplacian
__device__ int   g_deg[NN_];
__device__ int   g_rowptr[NN_+1];
__device__ int   g_colidx[NN_*NN_];

__device__ __forceinline__ unsigned f2tf32(float x) {
    unsigned r; asm("cvt.rna.tf32.f32 %0, %1;" : "=r"(r) : "f"(x)); return r;
}
__device__ __forceinline__ unsigned smem_u32(const void* p) {
    unsigned a;
    asm("{ .reg .u64 t; cvta.to.shared.u64 t, %1; cvt.u32.u64 %0, t; }" : "=r"(a) : "l"(p));
    return a;
}
__device__ __forceinline__ void cpasync16(unsigned dst, const void* src) {
    asm volatile("cp.async.cg.shared.global [%0], [%1], 16;" :: "r"(dst), "l"(src));
}

// ================= cp.async 3-stage pipelined TF32 GEMM, tile 128x64x32 =================
// 256 threads, 8 warps (4M x 2N), warp tile 32x32, accum 32 regs/thread.
// 2 CTAs/SM: smem 2*81.4KB = 163KB < 228KB; ~100 regs -> no spill at (256,2).
#define AST (128*36)
#define BST (32*68)
#define GC_SMEM ((3*(AST+BST))*4)

template<bool CVTA, bool CVTB>
__global__ void __launch_bounds__(256, 2) gemm_ca(
    const float* __restrict__ A, const float* __restrict__ B,
    const float* __restrict__ bias, float* __restrict__ C,
    float* __restrict__ Cr,
    int M, int N, int K)
{
    extern __shared__ float sm[];
    const float* As = sm;
    const float* Bs = sm + 3*AST;
    const unsigned smem_base = smem_u32(sm);

    const int tid = threadIdx.x;
    const int w   = tid >> 5, lane = tid & 31;
    const int g   = lane >> 2, tq = lane & 3;
    const int wm  = w & 3, wn = w >> 2;          // wn in 0..1
    const int bm  = blockIdx.y * 128, bn = blockIdx.x * 64;
    const int nck = K >> 5;

    float c[2][4][4];
    #pragma unroll
    for (int mt = 0; mt < 2; mt++)
        #pragma unroll
        for (int nt = 0; nt < 4; nt++)
            #pragma unroll
            for (int j = 0; j < 4; j++) c[mt][nt][j] = 0.f;

    auto stage_load = [&](int ck, int st) {
        const unsigned abase = smem_base + (unsigned)(st * AST) * 4u;
        const unsigned bbase = smem_base + (unsigned)(3*AST + st * BST) * 4u;
        #pragma unroll
        for (int i = 0; i < 4; i++) {
            int idx = tid + 256 * i;
            int m = idx >> 3, c4 = idx & 7;
            cpasync16(abase + (unsigned)(m * 36 + c4 * 4) * 4u,
                      A + (size_t)(bm + m) * K + ck * 32 + c4 * 4);
        }
        #pragma unroll
        for (int i = 0; i < 2; i++) {
            int idx = tid + 256 * i;
            int kr = idx >> 4, c4 = idx & 15;
            cpasync16(bbase + (unsigned)(kr * 68 + c4 * 4) * 4u,
                      B + (size_t)(ck * 32 + kr) * N + bn + c4 * 4);
        }
    };

    stage_load(0, 0);
    asm volatile("cp.async.commit_group;" ::: "memory");
    stage_load(1, 1);
    asm volatile("cp.async.commit_group;" ::: "memory");

    for (int ck = 0; ck < nck; ck++) {
        asm volatile("cp.async.wait_group 1;" ::: "memory");
        __syncthreads();
        if (ck + 2 < nck) stage_load(ck + 2, (ck + 2) % 3);
        asm volatile("cp.async.commit_group;" ::: "memory");

        const int st = ck % 3;
        const float* Ast = As + st * AST;
        const float* Bst = Bs + st * BST;
        #pragma unroll
        for (int ks = 0; ks < 4; ks++) {
            unsigned a[2][4], b[4][2];
            #pragma unroll
            for (int mt = 0; mt < 2; mt++) {
                const int r0 = wm * 32 + g + mt * 16;
                float v0 = Ast[r0 * 36 + ks * 8 + tq];
                float v1 = Ast[(r0 + 8) * 36 + ks * 8 + tq];
                float v2 = Ast[r0 * 36 + ks * 8 + tq + 4];
                float v3 = Ast[(r0 + 8) * 36 + ks * 8 + tq + 4];
                a[mt][0] = CVTA ? f2tf32(v0) : __float_as_uint(v0);
                a[mt][1] = CVTA ? f2tf32(v1) : __float_as_uint(v1);
                a[mt][2] = CVTA ? f2tf32(v2) : __float_as_uint(v2);
                a[mt][3] = CVTA ? f2tf32(v3) : __float_as_uint(v3);
            }
            const int bn0 = wn * 32 + g;
            #pragma unroll
            for (int nt = 0; nt < 4; nt++) {
                float u0 = Bst[(ks * 8 + tq) * 68 + bn0 + nt * 8];
                float u1 = Bst[(ks * 8 + tq + 4) * 68 + bn0 + nt * 8];
                b[nt][0] = CVTB ? f2tf32(u0) : __float_as_uint(u0);
                b[nt][1] = CVTB ? f2tf32(u1) : __float_as_uint(u1);
            }
            #pragma unroll
            for (int mt = 0; mt < 2; mt++)
                #pragma unroll
                for (int nt = 0; nt < 4; nt++)
                    asm volatile(
                        "mma.sync.aligned.m16n8k8.row.col.f32.tf32.tf32.f32 "
                        "{%0,%1,%2,%3}, {%4,%5,%6,%7}, {%8,%9}, {%0,%1,%2,%3};"
                        : "+f"(c[mt][nt][0]), "+f"(c[mt][nt][1]),
                          "+f"(c[mt][nt][2]), "+f"(c[mt][nt][3])
                        : "r"(a[mt][0]), "r"(a[mt][1]), "r"(a[mt][2]), "r"(a[mt][3]),
                          "r"(b[nt][0]), "r"(b[nt][1]));
        }
        __syncthreads();
    }

    #pragma unroll
    for (int mt = 0; mt < 2; mt++) {
        int row = bm + wm * 32 + mt * 16 + g;
        #pragma unroll
        for (int nt = 0; nt < 4; nt++) {
            int col = bn + wn * 32 + nt * 8 + tq * 2;
            float b0 = 0.f, b1 = 0.f;
            if (bias) { b0 = bias[col]; b1 = bias[col + 1]; }
            float o00 = c[mt][nt][0] + b0, o01 = c[mt][nt][1] + b1;
            float o10 = c[mt][nt][2] + b0, o11 = c[mt][nt][3] + b1;
            *(float2*)(C + (size_t)row * N + col)       = make_float2(o00, o01);
            *(float2*)(C + (size_t)(row + 8) * N + col) = make_float2(o10, o11);
            if (Cr) {
                *(float2*)(Cr + (size_t)row * N + col) =
                    make_float2(__uint_as_float(f2tf32(o00)), __uint_as_float(f2tf32(o01)));
                *(float2*)(Cr + (size_t)(row + 8) * N + col) =
                    make_float2(__uint_as_float(f2tf32(o10)), __uint_as_float(f2tf32(o11)));
            }
        }
    }
}

// ================= register-staged TF32 GEMM, B in [N,K] (for q@p^T) =================
#define GSMEM_BYTES (2 * 32 * 132 * 4 * 2)

__global__ void __launch_bounds__(256, 1) gemm_nt_tf32(
    const float* __restrict__ A, const float* __restrict__ B,
    float* __restrict__ C, int M, int N, int K)
{
    extern __shared__ unsigned smem_u[];
    unsigned (*As)[32][132] = reinterpret_cast<unsigned(*)[32][132]>(smem_u);
    unsigned (*Bs)[32][132] = reinterpret_cast<unsigned(*)[32][132]>(smem_u + 2*32*132);

    const int tid = threadIdx.x;
    const int w   = tid >> 5, lane = tid & 31;
    const int g   = lane >> 2, tq = lane & 3;
    const int wm  = w & 3, wn = w >> 2;
    const int bm  = blockIdx.y * 128, bn = blockIdx.x * 128;
    const int nck = K >> 5;

    float4 av[4], bv[4];
    float c[2][8][4];
    #pragma unroll
    for (int mt = 0; mt < 2; mt++)
        #pragma unroll
        for (int nt = 0; nt < 8; nt++)
            #pragma unroll
            for (int j = 0; j < 4; j++) c[mt][nt][j] = 0.f;

    for (int ck = 0; ck <= nck; ck++) {
        if (ck < nck) {
            #pragma unroll
            for (int i = 0; i < 4; i++) {
                int wt = w * 4 + i;
                int c4 = wt & 7;
                int r  = ((wt & 24) << 2) + lane;
                av[i] = *(const float4*)(A + (size_t)(bm + r) * K + ck * 32 + c4 * 4);
                bv[i] = *(const float4*)(B + (size_t)(bn + r) * K + ck * 32 + c4 * 4);
            }
        }
        if (ck > 0) {
            const int cb = (ck - 1) & 1;
            #pragma unroll
            for (int s = 0; s < 4; s++) {
                unsigned a[2][4], b[8][2];
                const unsigned* A0 = As[cb][s * 8 + tq];
                const unsigned* A4 = As[cb][s * 8 + tq + 4];
                const int am = wm * 32 + g;
                #pragma unroll
                for (int mt = 0; mt < 2; mt++) {
                    a[mt][0] = A0[am + mt * 16];
                    a[mt][1] = A0[am + mt * 16 + 8];
                    a[mt][2] = A4[am + mt * 16];
                    a[mt][3] = A4[am + mt * 16 + 8];
                }
                const unsigned* B0 = Bs[cb][s * 8 + tq];
                const unsigned* B4 = Bs[cb][s * 8 + tq + 4];
                const int bn0 = wn * 64 + g;
                #pragma unroll
                for (int nt = 0; nt < 8; nt++) {
                    b[nt][0] = B0[bn0 + nt * 8];
                    b[nt][1] = B4[bn0 + nt * 8];
                }
                #pragma unroll
                for (int mt = 0; mt < 2; mt++)
                    #pragma unroll
                    for (int nt = 0; nt < 8; nt++)
                        asm volatile(
                            "mma.sync.aligned.m16n8k8.row.col.f32.tf32.tf32.f32 "
                            "{%0,%1,%2,%3}, {%4,%5,%6,%7}, {%8,%9}, {%0,%1,%2,%3};"
                            : "+f"(c[mt][nt][0]), "+f"(c[mt][nt][1]),
                              "+f"(c[mt][nt][2]), "+f"(c[mt][nt][3])
                            : "r"(a[mt][0]), "r"(a[mt][1]), "r"(a[mt][2]), "r"(a[mt][3]),
                              "r"(b[nt][0]), "r"(b[nt][1]));
            }
        }
        if (ck < nck) {
            const int sb = ck & 1;
            #pragma unroll
            for (int i = 0; i < 4; i++) {
                int wt = w * 4 + i;
                int c4 = wt & 7;
                int r  = ((wt & 24) << 2) + lane;
                As[sb][c4 * 4 + 0][r] = f2tf32(av[i].x);
                As[sb][c4 * 4 + 1][r] = f2tf32(av[i].y);
                As[sb][c4 * 4 + 2][r] = f2tf32(av[i].z);
                As[sb][c4 * 4 + 3][r] = f2tf32(av[i].w);
                Bs[sb][c4 * 4 + 0][r] = f2tf32(bv[i].x);
                Bs[sb][c4 * 4 + 1][r] = f2tf32(bv[i].y);
                Bs[sb][c4 * 4 + 2][r] = f2tf32(bv[i].z);
                Bs[sb][c4 * 4 + 3][r] = f2tf32(bv[i].w);
            }
        }
        __syncthreads();
    }

    #pragma unroll
    for (int mt = 0; mt < 2; mt++) {
        int row = bm + wm * 32 + mt * 16 + g;
        #pragma unroll
        for (int nt = 0; nt < 8; nt++) {
            int col = bn + wn * 64 + nt * 8 + tq * 2;
            *(float2*)(C + (size_t)row * N + col) =
                make_float2(c[mt][nt][0], c[mt][nt][1]);
            *(float2*)(C + (size_t)(row + 8) * N + col) =
                make_float2(c[mt][nt][2], c[mt][nt][3]);
        }
    }
}

// ---------------- block reduction helpers (blockDim == 256) ----------------
__device__ __forceinline__ float blk_sum256(float v, float* red8) {
    int tid = threadIdx.x, lane = tid & 31, w = tid >> 5;
    #pragma unroll
    for (int o = 16; o; o >>= 1) v += __shfl_xor_sync(0xffffffffu, v, o);
    __syncthreads();
    if (lane == 0) red8[w] = v;
    __syncthreads();
    if (tid == 0) { float t = 0.f; for (int k = 0; k < 8; k++) t += red8[k]; red8[0] = t; }
    __syncthreads();
    return red8[0];
}

__device__ __forceinline__ float blk_max256(float v, float* red8) {
    int tid = threadIdx.x, lane = tid & 31, w = tid >> 5;
    #pragma unroll
    for (int o = 16; o; o >>= 1) v = fmaxf(v, __shfl_xor_sync(0xffffffffu, v, o));
    __syncthreads();
    if (lane == 0) red8[w] = v;
    __syncthreads();
    if (tid == 0) { float t = red8[0]; for (int k = 1; k < 8; k++) t = fmaxf(t, red8[k]); red8[0] = t; }
    __syncthreads();
    return red8[0];
}

// ---------------- misc kernels ----------------
__global__ void round_f4(const float4* __restrict__ src, float4* __restrict__ dst, int n4) {
    int i = blockIdx.x * blockDim.x + threadIdx.x;
    if (i < n4) {
        float4 v = src[i];
        dst[i] = make_float4(__uint_as_float(f2tf32(v.x)), __uint_as_float(f2tf32(v.y)),
                             __uint_as_float(f2tf32(v.z)), __uint_as_float(f2tf32(v.w)));
    }
}

// dst[f][c] = rna_tf32(gatW_layer[h][f][o]), c = h*128+o  (one layer per launch)
__global__ void reorder_gatw_r(const float* __restrict__ src, float* __restrict__ dst) {
    int idx = blockIdx.x * 256 + threadIdx.x;   // covers ED*GH = 1M
    int f = idx >> 10, c = idx & 1023, h = c >> 7, o = c & 127;
    float v = src[((size_t)h * 1024 + f) * 128 + o];
    dst[idx] = __uint_as_float(f2tf32(v));
}

// ---------------- CSR build (adj > 0) ----------------
__global__ void csr_count(const float* __restrict__ adj, int* __restrict__ deg) {
    int w = (blockIdx.x * blockDim.x + threadIdx.x) >> 5;
    int lane = threadIdx.x & 31;
    if (w >= NN_) return;
    const float* row = adj + (size_t)w * NN_;
    int cnt = 0;
    for (int c = 0; c < NN_/32; c++) {
        unsigned m = __ballot_sync(0xffffffffu, row[c*32 + lane] > 0.f);
        cnt += __popc(m);
    }
    if (lane == 0) deg[w] = cnt;
}

__global__ void csr_scan(const int* __restrict__ deg, int* __restrict__ rowptr) {
    __shared__ int ps[128];
    int t = threadIdx.x; // 128
    int s = 0;
    for (int i = 0; i < 16; i++) s += deg[t*16 + i];
    ps[t] = s;
    __syncthreads();
    if (t == 0) { int run = 0; for (int i = 0; i < 128; i++) { int v = ps[i]; ps[i] = run; run += v; } }
    __syncthreads();
    int run = ps[t];
    for (int i = 0; i < 16; i++) { rowptr[t*16 + i] = run; run += deg[t*16 + i]; }
    if (t == 127) rowptr[NN_] = run;
}

__global__ void csr_fill(const float* __restrict__ adj, const int* __restrict__ rowptr,
                         int* __restrict__ colidx) {
    int w = (blockIdx.x * blockDim.x + threadIdx.x) >> 5;
    int lane = threadIdx.x & 31;
    if (w >= NN_) return;
    const float* row = adj + (size_t)w * NN_;
    int base = rowptr[w];
    for (int c = 0; c < NN_/32; c++) {
        int j = c*32 + lane;
        bool p = row[j] > 0.f;
        unsigned m = __ballot_sync(0xffffffffu, p);
        if (p) colidx[base + __popc(m & ((1u << lane) - 1u))] = j;
        base += __popc(m);
    }
}

// ---------------- GAT pieces ----------------
__global__ void gat_scores(const float* __restrict__ Wh, const float* __restrict__ a1,
                           const float* __restrict__ a2, float* __restrict__ s1,
                           float* __restrict__ s2) {
    int n = blockIdx.x;
    int w = threadIdx.x >> 5, lane = threadIdx.x & 31;  // 8 warps = 8 heads
    const float* wr  = Wh + (size_t)n * GH + w * HD;
    const float* a1p = a1 + w * HD;
    const float* a2p = a2 + w * HD;
    float v1 = 0.f, v2 = 0.f;
    for (int o = lane; o < HD; o += 32) { float x = wr[o]; v1 += x * a1p[o]; v2 += x * a2p[o]; }
    #pragma unroll
    for (int o = 16; o; o >>= 1) {
        v1 += __shfl_xor_sync(0xffffffffu, v1, o);
        v2 += __shfl_xor_sync(0xffffffffu, v2, o);
    }
    if (lane == 0) { s1[n*NH + w] = v1; s2[n*NH + w] = v2; }
}

// aggregate + (fused) LayerNorm + ELU + residual-add -> out_x
__global__ void __launch_bounds__(256) gat_aggregate_ln(
    const float* __restrict__ Wh, const float* __restrict__ s1,
    const float* __restrict__ s2, const int* __restrict__ rowptr,
    const int* __restrict__ colidx,
    const float* __restrict__ lng, const float* __restrict__ lnb,
    const float* __restrict__ resid, float* __restrict__ out_x)
{
    const int i = blockIdx.x, tid = threadIdx.x, lane = tid & 31, w = tid >> 5;
    __shared__ float s1sh[8], mh[8], zh[8];
    __shared__ float wred[8][8];
    __shared__ float att[128*8];
    __shared__ int   jsh[128];
    __shared__ float red8[8];

    if (tid < 8) s1sh[tid] = s1[i*NH + tid];
    const int base = rowptr[i];
    const int deg  = rowptr[i+1] - base;
    __syncthreads();

    float lm[8];
    #pragma unroll
    for (int h = 0; h < 8; h++) lm[h] = -1e30f;
    for (int jj = tid; jj < deg; jj += 256) {
        int j = colidx[base + jj];
        #pragma unroll
        for (int h = 0; h < 8; h++) {
            float e = s1sh[h] + s2[j*NH + h];
            e = e > 0.f ? e : 0.2f * e;
            lm[h] = fmaxf(lm[h], e);
        }
    }
    #pragma unroll
    for (int h = 0; h < 8; h++) {
        #pragma unroll
        for (int o = 16; o; o >>= 1) lm[h] = fmaxf(lm[h], __shfl_xor_sync(0xffffffffu, lm[h], o));
    }
    if (lane == 0) {
        for (int h = 0; h < 8; h++) wred[w][h] = lm[h];
    }
    __syncthreads();
    if (tid < 8) {
        float m = wred[0][tid];
        for (int ww = 1; ww < 8; ww++) m = fmaxf(m, wred[ww][tid]);
        mh[tid] = m;
    }
    __syncthreads();

    float ls[8];
    #pragma unroll
    for (int h = 0; h < 8; h++) ls[h] = 0.f;
    for (int jj = tid; jj < deg; jj += 256) {
        int j = colidx[base + jj];
        #pragma unroll
        for (int h = 0; h < 8; h++) {
            float e = s1sh[h] + s2[j*NH + h];
            e = e > 0.f ? e : 0.2f * e;
            ls[h] += expf(e - mh[h]);
        }
    }
    #pragma unroll
    for (int h = 0; h < 8; h++) {
        #pragma unroll
        for (int o = 16; o; o >>= 1) ls[h] += __shfl_xor_sync(0xffffffffu, ls[h], o);
    }
    __syncthreads();
    if (lane == 0) {
        for (int h = 0; h < 8; h++) wred[w][h] = ls[h];
    }
    __syncthreads();
    if (tid < 8) {
        float s = 0.f;
        for (int ww = 0; ww < 8; ww++) s += wred[ww][tid];
        zh[tid] = s;
    }
    __syncthreads();

    float acc0 = 0.f, acc1 = 0.f, acc2 = 0.f, acc3 = 0.f;
    const int c0 = tid, c1 = tid + 256, c2 = tid + 512, c3 = tid + 768;
    const int h0 = c0 >> 7, h1 = c1 >> 7, h2 = c2 >> 7, h3 = c3 >> 7;
    for (int cs = 0; cs < deg; cs += 128) {
        const int nck = min(128, deg - cs);
        __syncthreads();
        for (int idx = tid; idx < nck; idx += 256) jsh[idx] = colidx[base + cs + idx];
        for (int idx = tid; idx < nck * 8; idx += 256) {
            int jj = idx >> 3, h = idx & 7;
            int j = colidx[base + cs + jj];
            float e = s1sh[h] + s2[j*NH + h];
            e = e > 0.f ? e : 0.2f * e;
            att[idx] = expf(e - mh[h]) / zh[h];
        }
        __syncthreads();
        int jj = 0;
        for (; jj + 1 < nck; jj += 2) {
            const float* wr0 = Wh + (size_t)jsh[jj] * GH;
            const float* at0 = att + jj * 8;
            const float* wr1 = Wh + (size_t)jsh[jj+1] * GH;
            const float* at1 = att + (jj+1) * 8;
            acc0 += at0[h0] * wr0[c0] + at1[h0] * wr1[c0];
            acc1 += at0[h1] * wr0[c1] + at1[h1] * wr1[c1];
            acc2 += at0[h2] * wr0[c2] + at1[h2] * wr1[c2];
            acc3 += at0[h3] * wr0[c3] + at1[h3] * wr1[c3];
        }
        if (jj < nck) {
            const float* wr = Wh + (size_t)jsh[jj] * GH;
            const float* at = att + jj * 8;
            acc0 += at[h0] * wr[c0];
            acc1 += at[h1] * wr[c1];
            acc2 += at[h2] * wr[c2];
            acc3 += at[h3] * wr[c3];
        }
    }
    __syncthreads();

    // ---- fused LayerNorm + ELU + residual ----
    float s = acc0 + acc1 + acc2 + acc3;
    s = blk_sum256(s, red8);
    float mu = s * (1.f/1024.f);
    float d0 = acc0 - mu, d1 = acc1 - mu, d2 = acc2 - mu, d3 = acc3 - mu;
    float q = d0*d0 + d1*d1 + d2*d2 + d3*d3;
    q = blk_sum256(q, red8);
    float rstd = rsqrtf(q * (1.f/1024.f) + 1e-5f);
    float* orow = out_x + (size_t)i * GH;
    const float* rrow = resid + (size_t)i * GH;
    {
        float y = d0 * rstd * lng[c0] + lnb[c0];
        float e = y > 0.f ? y : expm1f(y);
        orow[c0] = rrow[c0] + e;
        y = d1 * rstd * lng[c1] + lnb[c1];
        e = y > 0.f ? y : expm1f(y);
        orow[c1] = rrow[c1] + e;
        y = d2 * rstd * lng[c2] + lnb[c2];
        e = y > 0.f ? y : expm1f(y);
        orow[c2] = rrow[c2] + e;
        y = d3 * rstd * lng[c3] + lnb[c3];
        e = y > 0.f ? y : expm1f(y);
        orow[c3] = rrow[c3] + e;
    }
}

// ---------------- LN + gelu (MLP path) ----------------
__global__ void ln_act(const float* __restrict__ X, const float* __restrict__ g,
                       const float* __restrict__ b, float* __restrict__ out) {
    __shared__ float red8[8];
    int row = blockIdx.x, tid = threadIdx.x;
    const float* xr = X + (size_t)row * 1024;
    float v[4];
    #pragma unroll
    for (int k = 0; k < 4; k++) v[k] = xr[tid + 256*k];
    float s = v[0] + v[1] + v[2] + v[3];
    s = blk_sum256(s, red8);
    float mu = s * (1.f/1024.f);
    float q = 0.f;
    #pragma unroll
    for (int k = 0; k < 4; k++) { float d = v[k] - mu; q += d * d; }
    q = blk_sum256(q, red8);
    float rstd = rsqrtf(q * (1.f/1024.f) + 1e-5f);
    float* orow = out + (size_t)row * 1024;
    #pragma unroll
    for (int k = 0; k < 4; k++) {
        int c = tid + 256*k;
        float y = (v[k] - mu) * rstd * g[c] + b[c];
        orow[c] = y * 0.5f * (1.f + erff(y * 0.70710678118654752f));
    }
}

__global__ void l2norm_rows(const float* __restrict__ X, float* __restrict__ out) {
    __shared__ float red8[8];
    int row = blockIdx.x, tid = threadIdx.x;
    const float* xr = X + (size_t)row * 1024;
    float v[4];
    #pragma unroll
    for (int k = 0; k < 4; k++) v[k] = xr[tid + 256*k];
    float q = v[0]*v[0] + v[1]*v[1] + v[2]*v[2] + v[3]*v[3];
    q = blk_sum256(q, red8);
    float inv = 1.f / fmaxf(sqrtf(q), 1e-12f);
    float* orow = out + (size_t)row * 1024;
    #pragma unroll
    for (int k = 0; k < 4; k++) orow[tid + 256*k] = v[k] * inv;
}

__global__ void rowdot(const float* __restrict__ A, const float* __restrict__ B,
                       float* __restrict__ out) {
    __shared__ float red8[8];
    int row = blockIdx.x, tid = threadIdx.x;
    const float* ar = A + (size_t)row * 1024;
    const float* br = B + (size_t)row * 1024;
    float s = 0.f;
    #pragma unroll
    for (int k = 0; k < 4; k++) { int c = tid + 256*k; s += ar[c] * br[c]; }
    s = blk_sum256(s, red8);
    if (tid == 0) out[row] = s;
}

__global__ void lse_rows(const float* __restrict__ neg, float* __restrict__ infoRow) {
    __shared__ float red8[8];
    int row = blockIdx.x, tid = threadIdx.x;
    const float* r = neg + (size_t)row * 1024;
    float v[4];
    #pragma unroll
    for (int k = 0; k < 4; k++) v[k] = r[tid + 256*k] * 20.0f;  // 1/TEMP
    float m = fmaxf(fmaxf(v[0], v[1]), fmaxf(v[2], v[3]));
    m = blk_max256(m, red8);
    float s = 0.f;
    #pragma unroll
    for (int k = 0; k < 4; k++) s += expf(v[k] - m);
    s = blk_sum256(s, red8);
    if (tid == 0) {
        float pos = r[row] * 20.0f;
        float lse = m + logf(expf(pos - m) + s);
        infoRow[row] = lse - pos;
    }
}

__global__ void finalize_k(const float* __restrict__ infoRow, const float* __restrict__ lapRow,
                           float* __restrict__ out, int out_size) {
    __shared__ float ri[32], rl[32];
    int tid = threadIdx.x, lane = tid & 31, w = tid >> 5; // 1024 threads
    float vi = infoRow[tid];
    float vl = lapRow[tid] + lapRow[tid + 1024];
    #pragma unroll
    for (int o = 16; o; o >>= 1) {
        vi += __shfl_xor_sync(0xffffffffu, vi, o);
        vl += __shfl_xor_sync(0xffffffffu, vl, o);
    }
    if (lane == 0) { ri[w] = vi; rl[w] = vl; }
    __syncthreads();
    if (tid == 0) {
        float si = 0.f, sl = 0.f;
        for (int k = 0; k < 32; k++) { si += ri[k]; sl += rl[k]; }
        float info = si / 1024.f;
        float lap  = sl / 2048.f;
        float total = info + 0.1f * lap;
        out[0] = total;
        if (out_size > 1) out[1] = info;
        if (out_size > 2) out[2] = lap;
    }
}

// ---------------- host ----------------
extern "C" void kernel_launch(void* const* d_in, const int* in_sizes, int n_in,
                              void* d_out, int out_size) {
    const float* query = (const float*)d_in[0];
    const float* docs  = (const float*)d_in[1];
    const float* nodes = (const float*)d_in[2];
    const float* adj   = (const float*)d_in[3];
    const float* lapl  = (const float*)d_in[4];
    const float* qW1 = (const float*)d_in[5];  const float* qb1 = (const float*)d_in[6];
    const float* qg  = (const float*)d_in[7];  const float* qbt = (const float*)d_in[8];
    const float* qW2 = (const float*)d_in[9];  const float* qb2 = (const float*)d_in[10];
    const float* dW1 = (const float*)d_in[11]; const float* db1 = (const float*)d_in[12];
    const float* dg  = (const float*)d_in[13]; const float* dbt = (const float*)d_in[14];
    const float* dW2 = (const float*)d_in[15]; const float* db2 = (const float*)d_in[16];
    const float* gatW = (const float*)d_in[17];
    const float* a1   = (const float*)d_in[18];
    const float* a2   = (const float*)d_in[19];
    const float* ln_g = (const float*)d_in[20];
    const float* ln_b = (const float*)d_in[21];
    const float* poW  = (const float*)d_in[22];
    const float* pob  = (const float*)d_in[23];

    void* tp;
    float *px, *pWh, *ps1, *ps2, *pG, *pGr, *pLG;
    float *pt1, *pt2, *pt3, *pt4, *pq, *pp, *pneg, *pinfo, *plap;
    float *pWr, *ppoWr, *plaplr;
    int *pdeg, *prowptr, *pcolidx;
    cudaGetSymbolAddress(&tp, g_x);   px  = (float*)tp;
    cudaGetSymbolAddress(&tp, g_Wh);  pWh = (float*)tp;
    cudaGetSymbolAddress(&tp, g_s1);  ps1 = (float*)tp;
    cudaGetSymbolAddress(&tp, g_s2);  ps2 = (float*)tp;
    cudaGetSymbolAddress(&tp, g_G);   pG  = (float*)tp;
    cudaGetSymbolAddress(&tp, g_Gr);  pGr = (float*)tp;
    cudaGetSymbolAddress(&tp, g_LG);  pLG = (float*)tp;
    cudaGetSymbolAddress(&tp, g_t1);  pt1 = (float*)tp;
    cudaGetSymbolAddress(&tp, g_t2);  pt2 = (float*)tp;
    cudaGetSymbolAddress(&tp, g_t3);  pt3 = (float*)tp;
    cudaGetSymbolAddress(&tp, g_t4);  pt4 = (float*)tp;
    cudaGetSymbolAddress(&tp, g_q);   pq  = (float*)tp;
    cudaGetSymbolAddress(&tp, g_p);   pp  = (float*)tp;
    cudaGetSymbolAddress(&tp, g_neg); pneg = (float*)tp;
    cudaGetSymbolAddress(&tp, g_infoRow); pinfo = (float*)tp;
    cudaGetSymbolAddress(&tp, g_lapRow);  plap  = (float*)tp;
    cudaGetSymbolAddress(&tp, g_Wr);    pWr    = (float*)tp;
    cudaGetSymbolAddress(&tp, g_poWr);  ppoWr  = (float*)tp;
    cudaGetSymbolAddress(&tp, g_laplr); plaplr = (float*)tp;
    cudaGetSymbolAddress(&tp, g_deg);     pdeg    = (int*)tp;
    cudaGetSymbolAddress(&tp, g_rowptr);  prowptr = (int*)tp;
    cudaGetSymbolAddress(&tp, g_colidx);  pcolidx = (int*)tp;

    static cudaStream_t sQ = nullptr, sD = nullptr, sC = nullptr;
    static cudaEvent_t evRoot, evQ, evD, evC, evW0, evW, evSC;
    if (!sQ) {
        cudaStreamCreateWithFlags(&sQ, cudaStreamNonBlocking);
        cudaStreamCreateWithFlags(&sD, cudaStreamNonBlocking);
        cudaStreamCreateWithFlags(&sC, cudaStreamNonBlocking);
        cudaEventCreateWithFlags(&evRoot, cudaEventDisableTiming);
        cudaEventCreateWithFlags(&evQ, cudaEventDisableTiming);
        cudaEventCreateWithFlags(&evD, cudaEventDisableTiming);
        cudaEventCreateWithFlags(&evC, cudaEventDisableTiming);
        cudaEventCreateWithFlags(&evW0, cudaEventDisableTiming);
        cudaEventCreateWithFlags(&evW, cudaEventDisableTiming);
        cudaEventCreateWithFlags(&evSC, cudaEventDisableTiming);
        cudaFuncSetAttribute(gemm_ca<true,true>,  cudaFuncAttributeMaxDynamicSharedMemorySize, GC_SMEM);
        cudaFuncSetAttribute(gemm_ca<true,false>, cudaFuncAttributeMaxDynamicSharedMemorySize, GC_SMEM);
        cudaFuncSetAttribute(gemm_ca<false,false>,cudaFuncAttributeMaxDynamicSharedMemorySize, GC_SMEM);
        cudaFuncSetAttribute(gemm_nt_tf32, cudaFuncAttributeMaxDynamicSharedMemorySize, GSMEM_BYTES);
    }

    // fork point
    cudaEventRecord(evRoot, 0);
    cudaStreamWaitEvent(sQ, evRoot, 0);
    cudaStreamWaitEvent(sD, evRoot, 0);
    cudaStreamWaitEvent(sC, evRoot, 0);

    // ---- stream sC: per-layer gatW reorder+round, CSR, then big rounds; evSC joins all ----
    reorder_gatw_r<<<(ED*GH)/256, 256, 0, sC>>>(gatW, pWr);
    cudaEventRecord(evW0, sC);
    reorder_gatw_r<<<(ED*GH)/256, 256, 0, sC>>>(gatW + (size_t)NH*ED*HD, pWr + (size_t)ED*GH);
    reorder_gatw_r<<<(ED*GH)/256, 256, 0, sC>>>(gatW + (size_t)2*NH*ED*HD, pWr + (size_t)2*ED*GH);
    cudaEventRecord(evW, sC);
    csr_count<<<NN_*32/256, 256, 0, sC>>>(adj, pdeg);
    csr_scan<<<1, 128, 0, sC>>>(pdeg, prowptr);
    csr_fill<<<NN_*32/256, 256, 0, sC>>>(adj, prowptr, pcolidx);
    cudaEventRecord(evC, sC);
    round_f4<<<(GH*ED/4 + 255)/256, 256, 0, sC>>>((const float4*)poW, (float4*)ppoWr, GH*ED/4);
    round_f4<<<(NN_*NN_/4 + 255)/256, 256, 0, sC>>>((const float4*)lapl, (float4*)plaplr, NN_*NN_/4);
    cudaEventRecord(evSC, sC);

    // ---- stream sD: doc MLP -> p ----
    gemm_ca<true,true><<<dim3(ED/64, BB/128), 256, GC_SMEM, sD>>>(docs, dW1, db1, pt3, nullptr, BB, ED, ED);
    ln_act<<<BB, 256, 0, sD>>>(pt3, dg, dbt, pt4);
    gemm_ca<true,true><<<dim3(ED/64, BB/128), 256, GC_SMEM, sD>>>(pt4, dW2, db2, pt3, nullptr, BB, ED, ED);
    l2norm_rows<<<BB, 256, 0, sD>>>(pt3, pp);
    cudaEventRecord(evD, sD);

    // ---- stream sQ: query MLP -> q, then neg + lse ----
    gemm_ca<true,true><<<dim3(ED/64, BB/128), 256, GC_SMEM, sQ>>>(query, qW1, qb1, pt1, nullptr, BB, ED, ED);
    ln_act<<<BB, 256, 0, sQ>>>(pt1, qg, qbt, pt2);
    gemm_ca<true,true><<<dim3(ED/64, BB/128), 256, GC_SMEM, sQ>>>(pt2, qW2, qb2, pt1, nullptr, BB, ED, ED);
    l2norm_rows<<<BB, 256, 0, sQ>>>(pt1, pq);
    cudaStreamWaitEvent(sQ, evD, 0);
    gemm_nt_tf32<<<dim3(BB/128, BB/128), 256, GSMEM_BYTES, sQ>>>(pq, pp, pneg, BB, BB, ED);
    lse_rows<<<BB, 256, 0, sQ>>>(pneg, pinfo);
    cudaEventRecord(evQ, sQ);

    // ---- default stream: GNN chain ----
    cudaStreamWaitEvent(0, evW0, 0);
    for (int l = 0; l < NL; l++) {
        const float* xin = (l == 0) ? nodes : px;
        if (l == 1) cudaStreamWaitEvent(0, evW, 0);
        gemm_ca<true,false><<<dim3(GH/64, NN_/128), 256, GC_SMEM>>>(
            xin, pWr + (size_t)l*ED*GH, nullptr, pWh, nullptr, NN_, GH, ED);
        gat_scores<<<NN_, 256>>>(pWh, a1 + l*NH*HD, a2 + l*NH*HD, ps1, ps2);
        if (l == 0) cudaStreamWaitEvent(0, evC, 0);
        gat_aggregate_ln<<<NN_, 256>>>(pWh, ps1, ps2, prowptr, pcolidx,
                                       ln_g + l*GH, ln_b + l*GH, xin, px);
    }
    // G (fp32, for rowdot) + Gr (tf32-rounded, as B of the laplacian GEMM)
    cudaStreamWaitEvent(0, evSC, 0);
    gemm_ca<true,false><<<dim3(ED/64, NN_/128), 256, GC_SMEM>>>(px, ppoWr, pob, pG, pGr, NN_, ED, GH);
    gemm_ca<false,false><<<dim3(ED/64, NN_/128), 256, GC_SMEM>>>(plaplr, pGr, nullptr, pLG, nullptr, NN_, ED, NN_);
    rowdot<<<NN_, 256>>>(pG, pLG, plap);

    // ---- join + finalize ----
    cudaStreamWaitEvent(0, evQ, 0);
    finalize_k<<<1, 1024>>>(pinfo, plap, (float*)d_out, out_size);
}

// round 15
// speedup vs baseline: 1.0748x; 1.0748x over previous
#include <cuda_runtime.h>
#include <cuda_bf16.h>
#include <math.h>

// Problem dims (fixed per reference)
#define ED   1024
#define GH   1024
#define NL   3
#define NH   8
#define HD   128
#define NN_  2048   // graph nodes
#define BB   1024   // batch

// ---------------- scratch (static device globals; no allocation) ----------------
__device__ float g_x [NN_*GH];
__device__ float g_Wh[NN_*GH];
__device__ float g_s1[NN_*NH];
__device__ float g_s2[NN_*NH];
__device__ float g_G [NN_*ED];
__device__ float g_Gr[NN_*ED];
__device__ float g_LG[NN_*ED];
__device__ float g_t1[BB*ED];
__device__ float g_t2[BB*ED];
__device__ float g_t3[BB*ED];
__device__ float g_t4[BB*ED];
__device__ float g_q [BB*ED];
__device__ float g_p [BB*ED];
__device__ float g_neg[BB*BB];
__device__ float g_infoRow[BB];
__device__ float g_lapRow[NN_];
__device__ float g_Wr[NL*ED*GH];      // rounded+reordered gatW (all layers)
__device__ float g_poWr[GH*ED];       // rounded poW
__device__ float g_laplr[NN_*NN_];    // rounded laplacian
__device__ int   g_deg[NN_];
__device__ int   g_rowptr[NN_+1];
__device__ int   g_colidx[NN_*NN_];

__device__ __forceinline__ unsigned f2tf32(float x) {
    unsigned r; asm("cvt.rna.tf32.f32 %0, %1;" : "=r"(r) : "f"(x)); return r;
}
__device__ __forceinline__ unsigned smem_u32(const void* p) {
    unsigned a;
    asm("{ .reg .u64 t; cvta.to.shared.u64 t, %1; cvt.u32.u64 %0, t; }" : "=r"(a) : "l"(p));
    return a;
}
__device__ __forceinline__ void cpasync16(unsigned dst, const void* src) {
    asm volatile("cp.async.cg.shared.global [%0], [%1], 16;" :: "r"(dst), "l"(src));
}

// ================= cp.async 3-stage pipelined TF32 GEMM (B in [K,N]) =================
// R11-proven config: 128x128x32 tile, 256 threads, 1 CTA/SM.
// SCORES: additionally compute s1[n,h]=Wh_row·a1[h], s2=...·a2[h] in the epilogue
// (valid because each 128-wide N-tile == one head when N==GH).
#define AST (128*36)
#define BST (32*132)
#define GC_SMEM ((3*(AST+BST))*4)

template<bool CVTA, bool CVTB, bool SCORES>
__global__ void __launch_bounds__(256, 1) gemm_ca(
    const float* __restrict__ A, const float* __restrict__ B,
    const float* __restrict__ bias, float* __restrict__ C,
    float* __restrict__ Cr,
    const float* __restrict__ a1, const float* __restrict__ a2,
    float* __restrict__ s1, float* __restrict__ s2,
    int M, int N, int K)
{
    extern __shared__ float sm[];
    const float* As = sm;
    const float* Bs = sm + 3*AST;
    const unsigned smem_base = smem_u32(sm);
    __shared__ float spart[2][128][2];   // [wn][row][s1/s2]

    const int tid = threadIdx.x;
    const int w   = tid >> 5, lane = tid & 31;
    const int g   = lane >> 2, tq = lane & 3;
    const int wm  = w & 3, wn = w >> 2;
    const int bm  = blockIdx.y * 128, bn = blockIdx.x * 128;
    const int nck = K >> 5;

    float c[2][8][4];
    #pragma unroll
    for (int mt = 0; mt < 2; mt++)
        #pragma unroll
        for (int nt = 0; nt < 8; nt++)
            #pragma unroll
            for (int j = 0; j < 4; j++) c[mt][nt][j] = 0.f;

    auto stage_load = [&](int ck, int st) {
        const unsigned abase = smem_base + (unsigned)(st * AST) * 4u;
        const unsigned bbase = smem_base + (unsigned)(3*AST + st * BST) * 4u;
        #pragma unroll
        for (int i = 0; i < 4; i++) {
            int idx = tid + 256 * i;
            int m = idx >> 3, c4 = idx & 7;
            cpasync16(abase + (unsigned)(m * 36 + c4 * 4) * 4u,
                      A + (size_t)(bm + m) * K + ck * 32 + c4 * 4);
        }
        #pragma unroll
        for (int i = 0; i < 4; i++) {
            int idx = tid + 256 * i;
            int kr = idx >> 5, c4 = idx & 31;
            cpasync16(bbase + (unsigned)(kr * 132 + c4 * 4) * 4u,
                      B + (size_t)(ck * 32 + kr) * N + bn + c4 * 4);
        }
    };

    stage_load(0, 0);
    asm volatile("cp.async.commit_group;" ::: "memory");
    stage_load(1, 1);
    asm volatile("cp.async.commit_group;" ::: "memory");

    for (int ck = 0; ck < nck; ck++) {
        asm volatile("cp.async.wait_group 1;" ::: "memory");
        __syncthreads();
        if (ck + 2 < nck) stage_load(ck + 2, (ck + 2) % 3);
        asm volatile("cp.async.commit_group;" ::: "memory");

        const int st = ck % 3;
        const float* Ast = As + st * AST;
        const float* Bst = Bs + st * BST;
        #pragma unroll
        for (int ks = 0; ks < 4; ks++) {
            unsigned a[2][4], b[8][2];
            #pragma unroll
            for (int mt = 0; mt < 2; mt++) {
                const int r0 = wm * 32 + g + mt * 16;
                float v0 = Ast[r0 * 36 + ks * 8 + tq];
                float v1 = Ast[(r0 + 8) * 36 + ks * 8 + tq];
                float v2 = Ast[r0 * 36 + ks * 8 + tq + 4];
                float v3 = Ast[(r0 + 8) * 36 + ks * 8 + tq + 4];
                a[mt][0] = CVTA ? f2tf32(v0) : __float_as_uint(v0);
                a[mt][1] = CVTA ? f2tf32(v1) : __float_as_uint(v1);
                a[mt][2] = CVTA ? f2tf32(v2) : __float_as_uint(v2);
                a[mt][3] = CVTA ? f2tf32(v3) : __float_as_uint(v3);
            }
            const int bn0 = wn * 64 + g;
            #pragma unroll
            for (int nt = 0; nt < 8; nt++) {
                float u0 = Bst[(ks * 8 + tq) * 132 + bn0 + nt * 8];
                float u1 = Bst[(ks * 8 + tq + 4) * 132 + bn0 + nt * 8];
                b[nt][0] = CVTB ? f2tf32(u0) : __float_as_uint(u0);
                b[nt][1] = CVTB ? f2tf32(u1) : __float_as_uint(u1);
            }
            #pragma unroll
            for (int mt = 0; mt < 2; mt++)
                #pragma unroll
                for (int nt = 0; nt < 8; nt++)
                    asm volatile(
                        "mma.sync.aligned.m16n8k8.row.col.f32.tf32.tf32.f32 "
                        "{%0,%1,%2,%3}, {%4,%5,%6,%7}, {%8,%9}, {%0,%1,%2,%3};"
                        : "+f"(c[mt][nt][0]), "+f"(c[mt][nt][1]),
                          "+f"(c[mt][nt][2]), "+f"(c[mt][nt][3])
                        : "r"(a[mt][0]), "r"(a[mt][1]), "r"(a[mt][2]), "r"(a[mt][3]),
                          "r"(b[nt][0]), "r"(b[nt][1]));
        }
        __syncthreads();
    }

    float p1[4] = {0.f, 0.f, 0.f, 0.f};
    float p2[4] = {0.f, 0.f, 0.f, 0.f};
    const float* a1p = SCORES ? (a1 + (bn >> 7) * HD) : nullptr;
    const float* a2p = SCORES ? (a2 + (bn >> 7) * HD) : nullptr;

    #pragma unroll
    for (int mt = 0; mt < 2; mt++) {
        int row = bm + wm * 32 + mt * 16 + g;
        #pragma unroll
        for (int nt = 0; nt < 8; nt++) {
            int cc  = wn * 64 + nt * 8 + tq * 2;
            int col = bn + cc;
            float b0 = 0.f, b1 = 0.f;
            if (bias) { b0 = bias[col]; b1 = bias[col + 1]; }
            float o00 = c[mt][nt][0] + b0, o01 = c[mt][nt][1] + b1;
            float o10 = c[mt][nt][2] + b0, o11 = c[mt][nt][3] + b1;
            *(float2*)(C + (size_t)row * N + col)       = make_float2(o00, o01);
            *(float2*)(C + (size_t)(row + 8) * N + col) = make_float2(o10, o11);
            if (Cr) {
                *(float2*)(Cr + (size_t)row * N + col) =
                    make_float2(__uint_as_float(f2tf32(o00)), __uint_as_float(f2tf32(o01)));
                *(float2*)(Cr + (size_t)(row + 8) * N + col) =
                    make_float2(__uint_as_float(f2tf32(o10)), __uint_as_float(f2tf32(o11)));
            }
            if (SCORES) {
                float av0 = a1p[cc], av1 = a1p[cc + 1];
                float bv0 = a2p[cc], bv1 = a2p[cc + 1];
                p1[mt*2+0] += o00 * av0 + o01 * av1;
                p1[mt*2+1] += o10 * av0 + o11 * av1;
                p2[mt*2+0] += o00 * bv0 + o01 * bv1;
                p2[mt*2+1] += o10 * bv0 + o11 * bv1;
            }
        }
    }

    if (SCORES) {
        // reduce over tq (lane bits 0-1)
        #pragma unroll
        for (int o = 1; o <= 2; o <<= 1) {
            #pragma unroll
            for (int k = 0; k < 4; k++) {
                p1[k] += __shfl_xor_sync(0xffffffffu, p1[k], o);
                p2[k] += __shfl_xor_sync(0xffffffffu, p2[k], o);
            }
        }
        if (tq == 0) {
            #pragma unroll
            for (int mt = 0; mt < 2; mt++) {
                #pragma unroll
                for (int hh = 0; hh < 2; hh++) {
                    int r = wm * 32 + mt * 16 + g + hh * 8;
                    spart[wn][r][0] = p1[mt*2+hh];
                    spart[wn][r][1] = p2[mt*2+hh];
                }
            }
        }
        __syncthreads();
        if (tid < 128) {
            int head = bn >> 7;
            s1[(size_t)(bm + tid) * NH + head] = spart[0][tid][0] + spart[1][tid][0];
            s2[(size_t)(bm + tid) * NH + head] = spart[0][tid][1] + spart[1][tid][1];
        }
    }
}

// ================= register-staged TF32 GEMM, B in [N,K] (for q@p^T) =================
#define GSMEM_BYTES (2 * 32 * 132 * 4 * 2)

__global__ void __launch_bounds__(256, 1) gemm_nt_tf32(
    const float* __restrict__ A, const float* __restrict__ B,
    float* __restrict__ C, int M, int N, int K)
{
    extern __shared__ unsigned smem_u[];
    unsigned (*As)[32][132] = reinterpret_cast<unsigned(*)[32][132]>(smem_u);
    unsigned (*Bs)[32][132] = reinterpret_cast<unsigned(*)[32][132]>(smem_u + 2*32*132);

    const int tid = threadIdx.x;
    const int w   = tid >> 5, lane = tid & 31;
    const int g   = lane >> 2, tq = lane & 3;
    const int wm  = w & 3, wn = w >> 2;
    const int bm  = blockIdx.y * 128, bn = blockIdx.x * 128;
    const int nck = K >> 5;

    float4 av[4], bv[4];
    float c[2][8][4];
    #pragma unroll
    for (int mt = 0; mt < 2; mt++)
        #pragma unroll
        for (int nt = 0; nt < 8; nt++)
            #pragma unroll
            for (int j = 0; j < 4; j++) c[mt][nt][j] = 0.f;

    for (int ck = 0; ck <= nck; ck++) {
        if (ck < nck) {
            #pragma unroll
            for (int i = 0; i < 4; i++) {
                int wt = w * 4 + i;
                int c4 = wt & 7;
                int r  = ((wt & 24) << 2) + lane;
                av[i] = *(const float4*)(A + (size_t)(bm + r) * K + ck * 32 + c4 * 4);
                bv[i] = *(const float4*)(B + (size_t)(bn + r) * K + ck * 32 + c4 * 4);
            }
        }
        if (ck > 0) {
            const int cb = (ck - 1) & 1;
            #pragma unroll
            for (int s = 0; s < 4; s++) {
                unsigned a[2][4], b[8][2];
                const unsigned* A0 = As[cb][s * 8 + tq];
                const unsigned* A4 = As[cb][s * 8 + tq + 4];
                const int am = wm * 32 + g;
                #pragma unroll
                for (int mt = 0; mt < 2; mt++) {
                    a[mt][0] = A0[am + mt * 16];
                    a[mt][1] = A0[am + mt * 16 + 8];
                    a[mt][2] = A4[am + mt * 16];
                    a[mt][3] = A4[am + mt * 16 + 8];
                }
                const unsigned* B0 = Bs[cb][s * 8 + tq];
                const unsigned* B4 = Bs[cb][s * 8 + tq + 4];
                const int bn0 = wn * 64 + g;
                #pragma unroll
                for (int nt = 0; nt < 8; nt++) {
                    b[nt][0] = B0[bn0 + nt * 8];
                    b[nt][1] = B4[bn0 + nt * 8];
                }
                #pragma unroll
                for (int mt = 0; mt < 2; mt++)
                    #pragma unroll
                    for (int nt = 0; nt < 8; nt++)
                        asm volatile(
                            "mma.sync.aligned.m16n8k8.row.col.f32.tf32.tf32.f32 "
                            "{%0,%1,%2,%3}, {%4,%5,%6,%7}, {%8,%9}, {%0,%1,%2,%3};"
                            : "+f"(c[mt][nt][0]), "+f"(c[mt][nt][1]),
                              "+f"(c[mt][nt][2]), "+f"(c[mt][nt][3])
                            : "r"(a[mt][0]), "r"(a[mt][1]), "r"(a[mt][2]), "r"(a[mt][3]),
                              "r"(b[nt][0]), "r"(b[nt][1]));
            }
        }
        if (ck < nck) {
            const int sb = ck & 1;
            #pragma unroll
            for (int i = 0; i < 4; i++) {
                int wt = w * 4 + i;
                int c4 = wt & 7;
                int r  = ((wt & 24) << 2) + lane;
                As[sb][c4 * 4 + 0][r] = f2tf32(av[i].x);
                As[sb][c4 * 4 + 1][r] = f2tf32(av[i].y);
                As[sb][c4 * 4 + 2][r] = f2tf32(av[i].z);
                As[sb][c4 * 4 + 3][r] = f2tf32(av[i].w);
                Bs[sb][c4 * 4 + 0][r] = f2tf32(bv[i].x);
                Bs[sb][c4 * 4 + 1][r] = f2tf32(bv[i].y);
                Bs[sb][c4 * 4 + 2][r] = f2tf32(bv[i].z);
                Bs[sb][c4 * 4 + 3][r] = f2tf32(bv[i].w);
            }
        }
        __syncthreads();
    }

    #pragma unroll
    for (int mt = 0; mt < 2; mt++) {
        int row = bm + wm * 32 + mt * 16 + g;
        #pragma unroll
        for (int nt = 0; nt < 8; nt++) {
            int col = bn + wn * 64 + nt * 8 + tq * 2;
            *(float2*)(C + (size_t)row * N + col) =
                make_float2(c[mt][nt][0], c[mt][nt][1]);
            *(float2*)(C + (size_t)(row + 8) * N + col) =
                make_float2(c[mt][nt][2], c[mt][nt][3]);
        }
    }
}

// ---------------- block reduction helpers (blockDim == 256) ----------------
__device__ __forceinline__ float blk_sum256(float v, float* red8) {
    int tid = threadIdx.x, lane = tid & 31, w = tid >> 5;
    #pragma unroll
    for (int o = 16; o; o >>= 1) v += __shfl_xor_sync(0xffffffffu, v, o);
    __syncthreads();
    if (lane == 0) red8[w] = v;
    __syncthreads();
    if (tid == 0) { float t = 0.f; for (int k = 0; k < 8; k++) t += red8[k]; red8[0] = t; }
    __syncthreads();
    return red8[0];
}

__device__ __forceinline__ float blk_max256(float v, float* red8) {
    int tid = threadIdx.x, lane = tid & 31, w = tid >> 5;
    #pragma unroll
    for (int o = 16; o; o >>= 1) v = fmaxf(v, __shfl_xor_sync(0xffffffffu, v, o));
    __syncthreads();
    if (lane == 0) red8[w] = v;
    __syncthreads();
    if (tid == 0) { float t = red8[0]; for (int k = 1; k < 8; k++) t = fmaxf(t, red8[k]); red8[0] = t; }
    __syncthreads();
    return red8[0];
}

// ---------------- misc kernels ----------------
__global__ void round_f4(const float4* __restrict__ src, float4* __restrict__ dst, int n4) {
    int i = blockIdx.x * blockDim.x + threadIdx.x;
    if (i < n4) {
        float4 v = src[i];
        dst[i] = make_float4(__uint_as_float(f2tf32(v.x)), __uint_as_float(f2tf32(v.y)),
                             __uint_as_float(f2tf32(v.z)), __uint_as_float(f2tf32(v.w)));
    }
}

// dst[f][c] = rna_tf32(gatW_layer[h][f][o]), c = h*128+o  (one layer per launch)
__global__ void reorder_gatw_r(const float* __restrict__ src, float* __restrict__ dst) {
    int idx = blockIdx.x * 256 + threadIdx.x;   // covers ED*GH = 1M
    int f = idx >> 10, c = idx & 1023, h = c >> 7, o = c & 127;
    float v = src[((size_t)h * 1024 + f) * 128 + o];
    dst[idx] = __uint_as_float(f2tf32(v));
}

// ---------------- CSR build (adj > 0) ----------------
__global__ void csr_count(const float* __restrict__ adj, int* __restrict__ deg) {
    int w = (blockIdx.x * blockDim.x + threadIdx.x) >> 5;
    int lane = threadIdx.x & 31;
    if (w >= NN_) return;
    const float* row = adj + (size_t)w * NN_;
    int cnt = 0;
    for (int c = 0; c < NN_/32; c++) {
        unsigned m = __ballot_sync(0xffffffffu, row[c*32 + lane] > 0.f);
        cnt += __popc(m);
    }
    if (lane == 0) deg[w] = cnt;
}

__global__ void csr_scan(const int* __restrict__ deg, int* __restrict__ rowptr) {
    __shared__ int ps[128];
    int t = threadIdx.x; // 128
    int s = 0;
    for (int i = 0; i < 16; i++) s += deg[t*16 + i];
    ps[t] = s;
    __syncthreads();
    if (t == 0) { int run = 0; for (int i = 0; i < 128; i++) { int v = ps[i]; ps[i] = run; run += v; } }
    __syncthreads();
    int run = ps[t];
    for (int i = 0; i < 16; i++) { rowptr[t*16 + i] = run; run += deg[t*16 + i]; }
    if (t == 127) rowptr[NN_] = run;
}

__global__ void csr_fill(const float* __restrict__ adj, const int* __restrict__ rowptr,
                         int* __restrict__ colidx) {
    int w = (blockIdx.x * blockDim.x + threadIdx.x) >> 5;
    int lane = threadIdx.x & 31;
    if (w >= NN_) return;
    const float* row = adj + (size_t)w * NN_;
    int base = rowptr[w];
    for (int c = 0; c < NN_/32; c++) {
        int j = c*32 + lane;
        bool p = row[j] > 0.f;
        unsigned m = __ballot_sync(0xffffffffu, p);
        if (p) colidx[base + __popc(m & ((1u << lane) - 1u))] = j;
        base += __popc(m);
    }
}

// ---------------- GAT aggregate + fused LayerNorm + ELU + residual ----------------
__global__ void __launch_bounds__(256) gat_aggregate_ln(
    const float* __restrict__ Wh, const float* __restrict__ s1,
    const float* __restrict__ s2, const int* __restrict__ rowptr,
    const int* __restrict__ colidx,
    const float* __restrict__ lng, const float* __restrict__ lnb,
    const float* __restrict__ resid, float* __restrict__ out_x)
{
    const int i = blockIdx.x, tid = threadIdx.x, lane = tid & 31, w = tid >> 5;
    __shared__ float s1sh[8], mh[8], zh[8];
    __shared__ float wred[8][8];
    __shared__ float att[128*8];
    __shared__ int   jsh[128];
    __shared__ float red8[8];

    if (tid < 8) s1sh[tid] = s1[i*NH + tid];
    const int base = rowptr[i];
    const int deg  = rowptr[i+1] - base;
    __syncthreads();

    float lm[8];
    #pragma unroll
    for (int h = 0; h < 8; h++) lm[h] = -1e30f;
    for (int jj = tid; jj < deg; jj += 256) {
        int j = colidx[base + jj];
        #pragma unroll
        for (int h = 0; h < 8; h++) {
            float e = s1sh[h] + s2[j*NH + h];
            e = e > 0.f ? e : 0.2f * e;
            lm[h] = fmaxf(lm[h], e);
        }
    }
    #pragma unroll
    for (int h = 0; h < 8; h++) {
        #pragma unroll
        for (int o = 16; o; o >>= 1) lm[h] = fmaxf(lm[h], __shfl_xor_sync(0xffffffffu, lm[h], o));
    }
    if (lane == 0) {
        for (int h = 0; h < 8; h++) wred[w][h] = lm[h];
    }
    __syncthreads();
    if (tid < 8) {
        float m = wred[0][tid];
        for (int ww = 1; ww < 8; ww++) m = fmaxf(m, wred[ww][tid]);
        mh[tid] = m;
    }
    __syncthreads();

    float ls[8];
    #pragma unroll
    for (int h = 0; h < 8; h++) ls[h] = 0.f;
    for (int jj = tid; jj < deg; jj += 256) {
        int j = colidx[base + jj];
        #pragma unroll
        for (int h = 0; h < 8; h++) {
            float e = s1sh[h] + s2[j*NH + h];
            e = e > 0.f ? e : 0.2f * e;
            ls[h] += expf(e - mh[h]);
        }
    }
    #pragma unroll
    for (int h = 0; h < 8; h++) {
        #pragma unroll
        for (int o = 16; o; o >>= 1) ls[h] += __shfl_xor_sync(0xffffffffu, ls[h], o);
    }
    __syncthreads();
    if (lane == 0) {
        for (int h = 0; h < 8; h++) wred[w][h] = ls[h];
    }
    __syncthreads();
    if (tid < 8) {
        float s = 0.f;
        for (int ww = 0; ww < 8; ww++) s += wred[ww][tid];
        zh[tid] = s;
    }
    __syncthreads();

    float acc0 = 0.f, acc1 = 0.f, acc2 = 0.f, acc3 = 0.f;
    const int c0 = tid, c1 = tid + 256, c2 = tid + 512, c3 = tid + 768;
    const int h0 = c0 >> 7, h1 = c1 >> 7, h2 = c2 >> 7, h3 = c3 >> 7;
    for (int cs = 0; cs < deg; cs += 128) {
        const int nck = min(128, deg - cs);
        __syncthreads();
        for (int idx = tid; idx < nck; idx += 256) jsh[idx] = colidx[base + cs + idx];
        for (int idx = tid; idx < nck * 8; idx += 256) {
            int jj = idx >> 3, h = idx & 7;
            int j = colidx[base + cs + jj];
            float e = s1sh[h] + s2[j*NH + h];
            e = e > 0.f ? e : 0.2f * e;
            att[idx] = expf(e - mh[h]) / zh[h];
        }
        __syncthreads();
        int jj = 0;
        for (; jj + 1 < nck; jj += 2) {
            const float* wr0 = Wh + (size_t)jsh[jj] * GH;
            const float* at0 = att + jj * 8;
            const float* wr1 = Wh + (size_t)jsh[jj+1] * GH;
            const float* at1 = att + (jj+1) * 8;
            acc0 += at0[h0] * wr0[c0] + at1[h0] * wr1[c0];
            acc1 += at0[h1] * wr0[c1] + at1[h1] * wr1[c1];
            acc2 += at0[h2] * wr0[c2] + at1[h2] * wr1[c2];
            acc3 += at0[h3] * wr0[c3] + at1[h3] * wr1[c3];
        }
        if (jj < nck) {
            const float* wr = Wh + (size_t)jsh[jj] * GH;
            const float* at = att + jj * 8;
            acc0 += at[h0] * wr[c0];
            acc1 += at[h1] * wr[c1];
            acc2 += at[h2] * wr[c2];
            acc3 += at[h3] * wr[c3];
        }
    }
    __syncthreads();

    float s = acc0 + acc1 + acc2 + acc3;
    s = blk_sum256(s, red8);
    float mu = s * (1.f/1024.f);
    float d0 = acc0 - mu, d1 = acc1 - mu, d2 = acc2 - mu, d3 = acc3 - mu;
    float q = d0*d0 + d1*d1 + d2*d2 + d3*d3;
    q = blk_sum256(q, red8);
    float rstd = rsqrtf(q * (1.f/1024.f) + 1e-5f);
    float* orow = out_x + (size_t)i * GH;
    const float* rrow = resid + (size_t)i * GH;
    {
        float y = d0 * rstd * lng[c0] + lnb[c0];
        float e = y > 0.f ? y : expm1f(y);
        orow[c0] = rrow[c0] + e;
        y = d1 * rstd * lng[c1] + lnb[c1];
        e = y > 0.f ? y : expm1f(y);
        orow[c1] = rrow[c1] + e;
        y = d2 * rstd * lng[c2] + lnb[c2];
        e = y > 0.f ? y : expm1f(y);
        orow[c2] = rrow[c2] + e;
        y = d3 * rstd * lng[c3] + lnb[c3];
        e = y > 0.f ? y : expm1f(y);
        orow[c3] = rrow[c3] + e;
    }
}

// ---------------- LN + gelu (MLP path) ----------------
__global__ void ln_act(const float* __restrict__ X, const float* __restrict__ g,
                       const float* __restrict__ b, float* __restrict__ out) {
    __shared__ float red8[8];
    int row = blockIdx.x, tid = threadIdx.x;
    const float* xr = X + (size_t)row * 1024;
    float v[4];
    #pragma unroll
    for (int k = 0; k < 4; k++) v[k] = xr[tid + 256*k];
    float s = v[0] + v[1] + v[2] + v[3];
    s = blk_sum256(s, red8);
    float mu = s * (1.f/1024.f);
    float q = 0.f;
    #pragma unroll
    for (int k = 0; k < 4; k++) { float d = v[k] - mu; q += d * d; }
    q = blk_sum256(q, red8);
    float rstd = rsqrtf(q * (1.f/1024.f) + 1e-5f);
    float* orow = out + (size_t)row * 1024;
    #pragma unroll
    for (int k = 0; k < 4; k++) {
        int c = tid + 256*k;
        float y = (v[k] - mu) * rstd * g[c] + b[c];
        orow[c] = y * 0.5f * (1.f + erff(y * 0.70710678118654752f));
    }
}

__global__ void l2norm_rows(const float* __restrict__ X, float* __restrict__ out) {
    __shared__ float red8[8];
    int row = blockIdx.x, tid = threadIdx.x;
    const float* xr = X + (size_t)row * 1024;
    float v[4];
    #pragma unroll
    for (int k = 0; k < 4; k++) v[k] = xr[tid + 256*k];
    float q = v[0]*v[0] + v[1]*v[1] + v[2]*v[2] + v[3]*v[3];
    q = blk_sum256(q, red8);
    float inv = 1.f / fmaxf(sqrtf(q), 1e-12f);
    float* orow = out + (size_t)row * 1024;
    #pragma unroll
    for (int k = 0; k < 4; k++) orow[tid + 256*k] = v[k] * inv;
}

__global__ void rowdot(const float* __restrict__ A, const float* __restrict__ B,
                       float* __restrict__ out) {
    __shared__ float red8[8];
    int row = blockIdx.x, tid = threadIdx.x;
    const float* ar = A + (size_t)row * 1024;
    const float* br = B + (size_t)row * 1024;
    float s = 0.f;
    #pragma unroll
    for (int k = 0; k < 4; k++) { int c = tid + 256*k; s += ar[c] * br[c]; }
    s = blk_sum256(s, red8);
    if (tid == 0) out[row] = s;
}

__global__ void lse_rows(const float* __restrict__ neg, float* __restrict__ infoRow) {
    __shared__ float red8[8];
    int row = blockIdx.x, tid = threadIdx.x;
    const float* r = neg + (size_t)row * 1024;
    float v[4];
    #pragma unroll
    for (int k = 0; k < 4; k++) v[k] = r[tid + 256*k] * 20.0f;  // 1/TEMP
    float m = fmaxf(fmaxf(v[0], v[1]), fmaxf(v[2], v[3]));
    m = blk_max256(m, red8);
    float s = 0.f;
    #pragma unroll
    for (int k = 0; k < 4; k++) s += expf(v[k] - m);
    s = blk_sum256(s, red8);
    if (tid == 0) {
        float pos = r[row] * 20.0f;
        float lse = m + logf(expf(pos - m) + s);
        infoRow[row] = lse - pos;
    }
}

__global__ void finalize_k(const float* __restrict__ infoRow, const float* __restrict__ lapRow,
                           float* __restrict__ out, int out_size) {
    __shared__ float ri[32], rl[32];
    int tid = threadIdx.x, lane = tid & 31, w = tid >> 5; // 1024 threads
    float vi = infoRow[tid];
    float vl = lapRow[tid] + lapRow[tid + 1024];
    #pragma unroll
    for (int o = 16; o; o >>= 1) {
        vi += __shfl_xor_sync(0xffffffffu, vi, o);
        vl += __shfl_xor_sync(0xffffffffu, vl, o);
    }
    if (lane == 0) { ri[w] = vi; rl[w] = vl; }
    __syncthreads();
    if (tid == 0) {
        float si = 0.f, sl = 0.f;
        for (int k = 0; k < 32; k++) { si += ri[k]; sl += rl[k]; }
        float info = si / 1024.f;
        float lap  = sl / 2048.f;
        float total = info + 0.1f * lap;
        out[0] = total;
        if (out_size > 1) out[1] = info;
        if (out_size > 2) out[2] = lap;
    }
}

// ---------------- host ----------------
extern "C" void kernel_launch(void* const* d_in, const int* in_sizes, int n_in,
                              void* d_out, int out_size) {
    const float* query = (const float*)d_in[0];
    const float* docs  = (const float*)d_in[1];
    const float* nodes = (const float*)d_in[2];
    const float* adj   = (const float*)d_in[3];
    const float* lapl  = (const float*)d_in[4];
    const float* qW1 = (const float*)d_in[5];  const float* qb1 = (const float*)d_in[6];
    const float* qg  = (const float*)d_in[7];  const float* qbt = (const float*)d_in[8];
    const float* qW2 = (const float*)d_in[9];  const float* qb2 = (const float*)d_in[10];
    const float* dW1 = (const float*)d_in[11]; const float* db1 = (const float*)d_in[12];
    const float* dg  = (const float*)d_in[13]; const float* dbt = (const float*)d_in[14];
    const float* dW2 = (const float*)d_in[15]; const float* db2 = (const float*)d_in[16];
    const float* gatW = (const float*)d_in[17];
    const float* a1   = (const float*)d_in[18];
    const float* a2   = (const float*)d_in[19];
    const float* ln_g = (const float*)d_in[20];
    const float* ln_b = (const float*)d_in[21];
    const float* poW  = (const float*)d_in[22];
    const float* pob  = (const float*)d_in[23];

    void* tp;
    float *px, *pWh, *ps1, *ps2, *pG, *pGr, *pLG;
    float *pt1, *pt2, *pt3, *pt4, *pq, *pp, *pneg, *pinfo, *plap;
    float *pWr, *ppoWr, *plaplr;
    int *pdeg, *prowptr, *pcolidx;
    cudaGetSymbolAddress(&tp, g_x);   px  = (float*)tp;
    cudaGetSymbolAddress(&tp, g_Wh);  pWh = (float*)tp;
    cudaGetSymbolAddress(&tp, g_s1);  ps1 = (float*)tp;
    cudaGetSymbolAddress(&tp, g_s2);  ps2 = (float*)tp;
    cudaGetSymbolAddress(&tp, g_G);   pG  = (float*)tp;
    cudaGetSymbolAddress(&tp, g_Gr);  pGr = (float*)tp;
    cudaGetSymbolAddress(&tp, g_LG);  pLG = (float*)tp;
    cudaGetSymbolAddress(&tp, g_t1);  pt1 = (float*)tp;
    cudaGetSymbolAddress(&tp, g_t2);  pt2 = (float*)tp;
    cudaGetSymbolAddress(&tp, g_t3);  pt3 = (float*)tp;
    cudaGetSymbolAddress(&tp, g_t4);  pt4 = (float*)tp;
    cudaGetSymbolAddress(&tp, g_q);   pq  = (float*)tp;
    cudaGetSymbolAddress(&tp, g_p);   pp  = (float*)tp;
    cudaGetSymbolAddress(&tp, g_neg); pneg = (float*)tp;
    cudaGetSymbolAddress(&tp, g_infoRow); pinfo = (float*)tp;
    cudaGetSymbolAddress(&tp, g_lapRow);  plap  = (float*)tp;
    cudaGetSymbolAddress(&tp, g_Wr);    pWr    = (float*)tp;
    cudaGetSymbolAddress(&tp, g_poWr);  ppoWr  = (float*)tp;
    cudaGetSymbolAddress(&tp, g_laplr); plaplr = (float*)tp;
    cudaGetSymbolAddress(&tp, g_deg);     pdeg    = (int*)tp;
    cudaGetSymbolAddress(&tp, g_rowptr);  prowptr = (int*)tp;
    cudaGetSymbolAddress(&tp, g_colidx);  pcolidx = (int*)tp;

    static cudaStream_t sQ = nullptr, sD = nullptr, sC = nullptr;
    static cudaEvent_t evRoot, evQ, evD, evC, evW0, evW, evSC;
    if (!sQ) {
        cudaStreamCreateWithFlags(&sQ, cudaStreamNonBlocking);
        cudaStreamCreateWithFlags(&sD, cudaStreamNonBlocking);
        cudaStreamCreateWithFlags(&sC, cudaStreamNonBlocking);
        cudaEventCreateWithFlags(&evRoot, cudaEventDisableTiming);
        cudaEventCreateWithFlags(&evQ, cudaEventDisableTiming);
        cudaEventCreateWithFlags(&evD, cudaEventDisableTiming);
        cudaEventCreateWithFlags(&evC, cudaEventDisableTiming);
        cudaEventCreateWithFlags(&evW0, cudaEventDisableTiming);
        cudaEventCreateWithFlags(&evW, cudaEventDisableTiming);
        cudaEventCreateWithFlags(&evSC, cudaEventDisableTiming);
        cudaFuncSetAttribute(gemm_ca<true,true,false>,  cudaFuncAttributeMaxDynamicSharedMemorySize, GC_SMEM);
        cudaFuncSetAttribute(gemm_ca<true,false,true>,  cudaFuncAttributeMaxDynamicSharedMemorySize, GC_SMEM);
        cudaFuncSetAttribute(gemm_ca<true,false,false>, cudaFuncAttributeMaxDynamicSharedMemorySize, GC_SMEM);
        cudaFuncSetAttribute(gemm_ca<false,false,false>,cudaFuncAttributeMaxDynamicSharedMemorySize, GC_SMEM);
        cudaFuncSetAttribute(gemm_nt_tf32, cudaFuncAttributeMaxDynamicSharedMemorySize, GSMEM_BYTES);
    }

    // fork point
    cudaEventRecord(evRoot, 0);
    cudaStreamWaitEvent(sQ, evRoot, 0);
    cudaStreamWaitEvent(sD, evRoot, 0);
    cudaStreamWaitEvent(sC, evRoot, 0);

    // ---- stream sC: per-layer gatW reorder+round, CSR, then big rounds; evSC joins all ----
    reorder_gatw_r<<<(ED*GH)/256, 256, 0, sC>>>(gatW, pWr);
    cudaEventRecord(evW0, sC);
    reorder_gatw_r<<<(ED*GH)/256, 256, 0, sC>>>(gatW + (size_t)NH*ED*HD, pWr + (size_t)ED*GH);
    reorder_gatw_r<<<(ED*GH)/256, 256, 0, sC>>>(gatW + (size_t)2*NH*ED*HD, pWr + (size_t)2*ED*GH);
    cudaEventRecord(evW, sC);
    csr_count<<<NN_*32/256, 256, 0, sC>>>(adj, pdeg);
    csr_scan<<<1, 128, 0, sC>>>(pdeg, prowptr);
    csr_fill<<<NN_*32/256, 256, 0, sC>>>(adj, prowptr, pcolidx);
    cudaEventRecord(evC, sC);
    round_f4<<<(GH*ED/4 + 255)/256, 256, 0, sC>>>((const float4*)poW, (float4*)ppoWr, GH*ED/4);
    round_f4<<<(NN_*NN_/4 + 255)/256, 256, 0, sC>>>((const float4*)lapl, (float4*)plaplr, NN_*NN_/4);
    cudaEventRecord(evSC, sC);

    // ---- stream sD: doc MLP -> p ----
    gemm_ca<true,true,false><<<dim3(ED/128, BB/128), 256, GC_SMEM, sD>>>(
        docs, dW1, db1, pt3, nullptr, nullptr, nullptr, nullptr, nullptr, BB, ED, ED);
    ln_act<<<BB, 256, 0, sD>>>(pt3, dg, dbt, pt4);
    gemm_ca<true,true,false><<<dim3(ED/128, BB/128), 256, GC_SMEM, sD>>>(
        pt4, dW2, db2, pt3, nullptr, nullptr, nullptr, nullptr, nullptr, BB, ED, ED);
    l2norm_rows<<<BB, 256, 0, sD>>>(pt3, pp);
    cudaEventRecord(evD, sD);

    // ---- stream sQ: query MLP -> q, then neg + lse ----
    gemm_ca<true,true,false><<<dim3(ED/128, BB/128), 256, GC_SMEM, sQ>>>(
        query, qW1, qb1, pt1, nullptr, nullptr, nullptr, nullptr, nullptr, BB, ED, ED);
    ln_act<<<BB, 256, 0, sQ>>>(pt1, qg, qbt, pt2);
    gemm_ca<true,true,false><<<dim3(ED/128, BB/128), 256, GC_SMEM, sQ>>>(
        pt2, qW2, qb2, pt1, nullptr, nullptr, nullptr, nullptr, nullptr, BB, ED, ED);
    l2norm_rows<<<BB, 256, 0, sQ>>>(pt1, pq);
    cudaStreamWaitEvent(sQ, evD, 0);
    gemm_nt_tf32<<<dim3(BB/128, BB/128), 256, GSMEM_BYTES, sQ>>>(pq, pp, pneg, BB, BB, ED);
    lse_rows<<<BB, 256, 0, sQ>>>(pneg, pinfo);
    cudaEventRecord(evQ, sQ);

    // ---- default stream: GNN chain (scores fused into GEMM epilogue) ----
    cudaStreamWaitEvent(0, evW0, 0);
    for (int l = 0; l < NL; l++) {
        const float* xin = (l == 0) ? nodes : px;
        if (l == 1) cudaStreamWaitEvent(0, evW, 0);
        gemm_ca<true,false,true><<<dim3(GH/128, NN_/128), 256, GC_SMEM>>>(
            xin, pWr + (size_t)l*ED*GH, nullptr, pWh, nullptr,
            a1 + l*NH*HD, a2 + l*NH*HD, ps1, ps2, NN_, GH, ED);
        if (l == 0) cudaStreamWaitEvent(0, evC, 0);
        gat_aggregate_ln<<<NN_, 256>>>(pWh, ps1, ps2, prowptr, pcolidx,
                                       ln_g + l*GH, ln_b + l*GH, xin, px);
    }
    // G (fp32, for rowdot) + Gr (tf32-rounded, as B of the laplacian GEMM)
    cudaStreamWaitEvent(0, evSC, 0);
    gemm_ca<true,false,false><<<dim3(ED/128, NN_/128), 256, GC_SMEM>>>(
        px, ppoWr, pob, pG, pGr, nullptr, nullptr, nullptr, nullptr, NN_, ED, GH);
    gemm_ca<false,false,false><<<dim3(ED/128, NN_/128), 256, GC_SMEM>>>(
        plaplr, pGr, nullptr, pLG, nullptr, nullptr, nullptr, nullptr, nullptr, NN_, ED, NN_);
    rowdot<<<NN_, 256>>>(pG, pLG, plap);

    // ---- join + finalize ----
    cudaStreamWaitEvent(0, evQ, 0);
    finalize_k<<<1, 1024>>>(pinfo, plap, (float*)d_out, out_size);
}